// round 1
// baseline (speedup 1.0000x reference)
#include <cuda_runtime.h>
#include <math.h>

#define B_ 4
#define T_ 1024
#define D_ 1024
#define H_ 16
#define HS 64

// Scratch (allocation-free rule: __device__ globals)
__device__ float g_q[B_*H_*T_*HS];
__device__ float g_k[B_*H_*T_*HS];
__device__ float g_v[B_*H_*T_*HS];
__device__ float g_y[B_*T_*D_];

// ---------------------------------------------------------------------------
// Kernel 1: fused QKV projection.
// grid (T/64, H, B), block (16,16). Each block: 64x64 tile of q,k,v for one
// (b, h). x tile loaded once per K-step, reused for 3 weight matrices.
// ---------------------------------------------------------------------------
__global__ __launch_bounds__(256) void qkv_kernel(
    const float* __restrict__ x,
    const float* __restrict__ Wq,
    const float* __restrict__ Wk,
    const float* __restrict__ Wv)
{
    const int tt = blockIdx.x * 64;
    const int h  = blockIdx.y;
    const int b  = blockIdx.z;
    const int tx = threadIdx.x, ty = threadIdx.y;
    const int tid = ty * 16 + tx;

    __shared__ float xs[64][33];
    __shared__ float ws[3][32][64];

    float aq[4][4] = {}, ak[4][4] = {}, av[4][4] = {};

    const float* xb  = x  + ((size_t)b * T_ + tt) * D_;
    const float* wqh = Wq + (size_t)h * D_ * HS;
    const float* wkh = Wk + (size_t)h * D_ * HS;
    const float* wvh = Wv + (size_t)h * D_ * HS;

    for (int k0 = 0; k0 < D_; k0 += 32) {
        // load x tile [64 t][32 c]
        {
            int col = tid & 31, r0 = tid >> 5;
            #pragma unroll
            for (int r = 0; r < 8; r++) {
                int row = r0 + r * 8;
                xs[row][col] = xb[(size_t)row * D_ + k0 + col];
            }
        }
        // load 3 weight tiles [32 c][64 s]
        {
            int col = tid & 63, r0 = tid >> 6;
            #pragma unroll
            for (int r = 0; r < 8; r++) {
                int row = r0 + r * 4;
                size_t off = (size_t)(k0 + row) * HS + col;
                ws[0][row][col] = wqh[off];
                ws[1][row][col] = wkh[off];
                ws[2][row][col] = wvh[off];
            }
        }
        __syncthreads();

        #pragma unroll
        for (int kk = 0; kk < 32; kk++) {
            float a[4];
            #pragma unroll
            for (int i = 0; i < 4; i++) a[i] = xs[ty * 4 + i][kk];
            float4 bq = *(const float4*)&ws[0][kk][tx * 4];
            float4 bk = *(const float4*)&ws[1][kk][tx * 4];
            float4 bv = *(const float4*)&ws[2][kk][tx * 4];
            #pragma unroll
            for (int i = 0; i < 4; i++) {
                aq[i][0] += a[i] * bq.x; aq[i][1] += a[i] * bq.y;
                aq[i][2] += a[i] * bq.z; aq[i][3] += a[i] * bq.w;
                ak[i][0] += a[i] * bk.x; ak[i][1] += a[i] * bk.y;
                ak[i][2] += a[i] * bk.z; ak[i][3] += a[i] * bk.w;
                av[i][0] += a[i] * bv.x; av[i][1] += a[i] * bv.y;
                av[i][2] += a[i] * bv.z; av[i][3] += a[i] * bv.w;
            }
        }
        __syncthreads();
    }

    size_t base = ((size_t)(b * H_ + h) * T_ + tt + ty * 4) * HS + tx * 4;
    #pragma unroll
    for (int i = 0; i < 4; i++) {
        *(float4*)&g_q[base + (size_t)i * HS] = make_float4(aq[i][0], aq[i][1], aq[i][2], aq[i][3]);
        *(float4*)&g_k[base + (size_t)i * HS] = make_float4(ak[i][0], ak[i][1], ak[i][2], ak[i][3]);
        *(float4*)&g_v[base + (size_t)i * HS] = make_float4(av[i][0], av[i][1], av[i][2], av[i][3]);
    }
}

// ---------------------------------------------------------------------------
// Kernel 2: causal flash attention (fp32, online softmax).
// grid (T/64, H, B), block (16,16). 64-query tile per block; loops over
// K/V tiles 0..qt (causal tile skipping). Dynamic smem: Qs,Ks,Vs,Ps (stride 68).
// Writes concat-head layout Y[b][t][h*64+d].
// ---------------------------------------------------------------------------
#define ST 68
__global__ __launch_bounds__(256) void attn_kernel()
{
    extern __shared__ float sm[];
    float* Qs = sm;
    float* Ks = Qs + 64 * ST;
    float* Vs = Ks + 64 * ST;
    float* Ps = Vs + 64 * ST;

    const int qt = blockIdx.x;
    const int h  = blockIdx.y;
    const int b  = blockIdx.z;
    const int tx = threadIdx.x, ty = threadIdx.y;
    const int tid = ty * 16 + tx;

    const float* qp = g_q + ((size_t)(b * H_ + h) * T_ + qt * 64) * HS;
    const float* kp = g_k + (size_t)(b * H_ + h) * T_ * HS;
    const float* vp = g_v + (size_t)(b * H_ + h) * T_ * HS;

    // load Q tile
    {
        int c4 = (tid & 15) * 4, r0 = tid >> 4;
        #pragma unroll
        for (int r = 0; r < 4; r++) {
            int row = r0 + r * 16;
            *(float4*)&Qs[row * ST + c4] = *(const float4*)&qp[(size_t)row * HS + c4];
        }
    }

    float m_i[4], l_i[4], o[4][4] = {};
    #pragma unroll
    for (int i = 0; i < 4; i++) { m_i[i] = -INFINITY; l_i[i] = 0.f; }
    const float scale = 0.125f;  // 1/sqrt(64)

    for (int kt = 0; kt <= qt; kt++) {
        // load K, V tiles
        {
            const float* kpt = kp + (size_t)kt * 64 * HS;
            const float* vpt = vp + (size_t)kt * 64 * HS;
            int c4 = (tid & 15) * 4, r0 = tid >> 4;
            #pragma unroll
            for (int r = 0; r < 4; r++) {
                int row = r0 + r * 16;
                *(float4*)&Ks[row * ST + c4] = *(const float4*)&kpt[(size_t)row * HS + c4];
                *(float4*)&Vs[row * ST + c4] = *(const float4*)&vpt[(size_t)row * HS + c4];
            }
        }
        __syncthreads();

        // S = Q @ K^T
        float s[4][4] = {};
        #pragma unroll
        for (int ss = 0; ss < 64; ss += 4) {
            float4 q4[4], k4[4];
            #pragma unroll
            for (int i = 0; i < 4; i++) q4[i] = *(const float4*)&Qs[(ty * 4 + i) * ST + ss];
            #pragma unroll
            for (int j = 0; j < 4; j++) k4[j] = *(const float4*)&Ks[(tx * 4 + j) * ST + ss];
            #pragma unroll
            for (int i = 0; i < 4; i++)
                #pragma unroll
                for (int j = 0; j < 4; j++) {
                    s[i][j] += q4[i].x * k4[j].x + q4[i].y * k4[j].y
                             + q4[i].z * k4[j].z + q4[i].w * k4[j].w;
                }
        }

        // scale + causal mask (diagonal tile only)
        #pragma unroll
        for (int i = 0; i < 4; i++)
            #pragma unroll
            for (int j = 0; j < 4; j++) {
                s[i][j] *= scale;
                if (kt == qt && (tx * 4 + j) > (ty * 4 + i)) s[i][j] = -INFINITY;
            }

        // online softmax
        float mnew[4], corr[4];
        #pragma unroll
        for (int i = 0; i < 4; i++) {
            float mx = fmaxf(fmaxf(s[i][0], s[i][1]), fmaxf(s[i][2], s[i][3]));
            #pragma unroll
            for (int off = 8; off > 0; off >>= 1)
                mx = fmaxf(mx, __shfl_xor_sync(0xffffffffu, mx, off));
            mnew[i] = fmaxf(m_i[i], mx);
            corr[i] = __expf(m_i[i] - mnew[i]);
            m_i[i]  = mnew[i];
        }
        #pragma unroll
        for (int i = 0; i < 4; i++) {
            float rs = 0.f;
            #pragma unroll
            for (int j = 0; j < 4; j++) {
                float p = __expf(s[i][j] - mnew[i]);
                s[i][j] = p;
                rs += p;
            }
            #pragma unroll
            for (int off = 8; off > 0; off >>= 1)
                rs += __shfl_xor_sync(0xffffffffu, rs, off);
            l_i[i] = l_i[i] * corr[i] + rs;
            #pragma unroll
            for (int j = 0; j < 4; j++) o[i][j] *= corr[i];
        }

        // P -> shared
        #pragma unroll
        for (int i = 0; i < 4; i++)
            *(float4*)&Ps[(ty * 4 + i) * ST + tx * 4] =
                make_float4(s[i][0], s[i][1], s[i][2], s[i][3]);
        __syncthreads();

        // O += P @ V
        #pragma unroll 8
        for (int kk = 0; kk < 64; kk++) {
            float p_[4];
            #pragma unroll
            for (int i = 0; i < 4; i++) p_[i] = Ps[(ty * 4 + i) * ST + kk];
            float4 v4 = *(const float4*)&Vs[kk * ST + tx * 4];
            #pragma unroll
            for (int i = 0; i < 4; i++) {
                o[i][0] += p_[i] * v4.x; o[i][1] += p_[i] * v4.y;
                o[i][2] += p_[i] * v4.z; o[i][3] += p_[i] * v4.w;
            }
        }
        __syncthreads();  // protect Ks/Vs/Ps before next tile
    }

    // epilogue: normalize + write concat-head layout
    #pragma unroll
    for (int i = 0; i < 4; i++) {
        float inv = 1.f / l_i[i];
        int t = qt * 64 + ty * 4 + i;
        *(float4*)&g_y[((size_t)b * T_ + t) * D_ + h * 64 + tx * 4] =
            make_float4(o[i][0] * inv, o[i][1] * inv, o[i][2] * inv, o[i][3] * inv);
    }
}

// ---------------------------------------------------------------------------
// Kernel 3: output projection  out = Y @ Wo^T + bo.
// grid (B*T/64, D/64), block (16,16).
// ---------------------------------------------------------------------------
__global__ __launch_bounds__(256) void oproj_kernel(
    const float* __restrict__ Wo,
    const float* __restrict__ bo,
    float* __restrict__ out)
{
    const int n0 = blockIdx.x * 64;
    const int m0 = blockIdx.y * 64;
    const int tx = threadIdx.x, ty = threadIdx.y;
    const int tid = ty * 16 + tx;

    __shared__ float as_[64][33];
    __shared__ float bs[32][65];

    float acc[4][4] = {};

    for (int k0 = 0; k0 < D_; k0 += 32) {
        int col = tid & 31, r0 = tid >> 5;
        #pragma unroll
        for (int r = 0; r < 8; r++) {
            int row = r0 + r * 8;
            as_[row][col] = g_y[(size_t)(n0 + row) * D_ + k0 + col];
            bs[col][row]  = Wo[(size_t)(m0 + row) * D_ + k0 + col];
        }
        __syncthreads();

        #pragma unroll
        for (int kk = 0; kk < 32; kk++) {
            float a[4], bb[4];
            #pragma unroll
            for (int i = 0; i < 4; i++) a[i]  = as_[ty * 4 + i][kk];
            #pragma unroll
            for (int j = 0; j < 4; j++) bb[j] = bs[kk][tx * 4 + j];
            #pragma unroll
            for (int i = 0; i < 4; i++)
                #pragma unroll
                for (int j = 0; j < 4; j++) acc[i][j] += a[i] * bb[j];
        }
        __syncthreads();
    }

    #pragma unroll
    for (int i = 0; i < 4; i++) {
        int n = n0 + ty * 4 + i;
        #pragma unroll
        for (int j = 0; j < 4; j++) {
            int m = m0 + tx * 4 + j;
            out[(size_t)n * D_ + m] = acc[i][j] + bo[m];
        }
    }
}

// ---------------------------------------------------------------------------
extern "C" void kernel_launch(void* const* d_in, const int* in_sizes, int n_in,
                              void* d_out, int out_size)
{
    const float* x  = (const float*)d_in[0];
    const float* Wq = (const float*)d_in[1];
    const float* Wk = (const float*)d_in[2];
    const float* Wv = (const float*)d_in[3];
    const float* Wo = (const float*)d_in[4];
    const float* bo = (const float*)d_in[5];
    float* out = (float*)d_out;

    const int ATTN_SMEM = 4 * 64 * ST * (int)sizeof(float);  // 69632 B
    cudaFuncSetAttribute(attn_kernel,
                         cudaFuncAttributeMaxDynamicSharedMemorySize, ATTN_SMEM);

    dim3 blk(16, 16);
    qkv_kernel<<<dim3(T_ / 64, H_, B_), blk>>>(x, Wq, Wk, Wv);
    attn_kernel<<<dim3(T_ / 64, H_, B_), blk, ATTN_SMEM>>>();
    oproj_kernel<<<dim3(B_ * T_ / 64, D_ / 64), blk>>>(Wo, bo, out);
}

// round 3
// speedup vs baseline: 1.5393x; 1.5393x over previous
#include <cuda_runtime.h>
#include <cuda_bf16.h>
#include <cstdint>
#include <math.h>

#define B_ 4
#define T_ 1024
#define D_ 1024
#define H_ 16
#define HS 64

// ---------------- device scratch (allocation-free rule) ----------------
__device__ float g_q[B_*H_*T_*HS];
__device__ float g_k[B_*H_*T_*HS];
__device__ float g_v[B_*H_*T_*HS];
__device__ __nv_bfloat16 g_xh[B_*T_*D_];
__device__ __nv_bfloat16 g_xl[B_*T_*D_];
__device__ __nv_bfloat16 g_wth[3*H_*HS*D_];   // [m][h][s][c]  K-major
__device__ __nv_bfloat16 g_wtl[3*H_*HS*D_];
__device__ __nv_bfloat16 g_yh[B_*T_*D_];
__device__ __nv_bfloat16 g_yl[B_*T_*D_];
__device__ __nv_bfloat16 g_woh[D_*D_];
__device__ __nv_bfloat16 g_wol[D_*D_];

// ---------------- helpers ----------------
__device__ __forceinline__ uint32_t smem_u32(const void* p) {
    uint32_t a;
    asm("{ .reg .u64 t; cvta.to.shared.u64 t, %1; cvt.u32.u64 %0, t; }" : "=r"(a) : "l"(p));
    return a;
}
__device__ __forceinline__ void cpasync16(uint32_t dst, const void* src) {
    asm volatile("cp.async.cg.shared.global [%0], [%1], 16;" :: "r"(dst), "l"(src) : "memory");
}
__device__ __forceinline__ void ldmx4(uint32_t* r, uint32_t addr) {
    asm volatile("ldmatrix.sync.aligned.m8n8.x4.shared.b16 {%0,%1,%2,%3}, [%4];"
                 : "=r"(r[0]), "=r"(r[1]), "=r"(r[2]), "=r"(r[3]) : "r"(addr));
}
__device__ __forceinline__ void mma16816(float* d, const uint32_t* a, uint32_t b0, uint32_t b1) {
    asm volatile(
        "mma.sync.aligned.m16n8k16.row.col.f32.bf16.bf16.f32 "
        "{%0,%1,%2,%3}, {%4,%5,%6,%7}, {%8,%9}, {%0,%1,%2,%3};"
        : "+f"(d[0]), "+f"(d[1]), "+f"(d[2]), "+f"(d[3])
        : "r"(a[0]), "r"(a[1]), "r"(a[2]), "r"(a[3]), "r"(b0), "r"(b1));
}

// ---------------------------------------------------------------------------
// fp32 -> bf16 hi/lo elementwise split
// ---------------------------------------------------------------------------
__global__ __launch_bounds__(256) void conv_pair(
    const float* __restrict__ src, __nv_bfloat16* __restrict__ dh,
    __nv_bfloat16* __restrict__ dl, int n)
{
    int i4 = (blockIdx.x * 256 + threadIdx.x) * 4;
    if (i4 >= n) return;
    float4 v = *(const float4*)(src + i4);
    float vv[4] = {v.x, v.y, v.z, v.w};
    __nv_bfloat16 hh[4], ll[4];
#pragma unroll
    for (int j = 0; j < 4; j++) {
        __nv_bfloat16 hi = __float2bfloat16(vv[j]);
        hh[j] = hi;
        ll[j] = __float2bfloat16(vv[j] - __bfloat162float(hi));
    }
    *(uint2*)(dh + i4) = *(uint2*)hh;
    *(uint2*)(dl + i4) = *(uint2*)ll;
}

// ---------------------------------------------------------------------------
// Wq/Wk/Wv [H][D][HS] -> Wt[m*16+h][s][c] K-major bf16 hi/lo (smem transpose)
// grid (D/32, HS/32, 48), block (32, 8)
// ---------------------------------------------------------------------------
__global__ __launch_bounds__(256) void conv_wt(
    const float* __restrict__ Wq, const float* __restrict__ Wk, const float* __restrict__ Wv)
{
    __shared__ float tile[32][33];
    int z = blockIdx.z;
    int m = z >> 4, h = z & 15;
    int c0 = blockIdx.x * 32, s0 = blockIdx.y * 32;
    int tx = threadIdx.x, ty = threadIdx.y;
    const float* W = (m == 0) ? Wq : (m == 1) ? Wk : Wv;
    const float* Wh_ = W + (size_t)h * D_ * HS;
#pragma unroll
    for (int i = 0; i < 4; i++) {
        int c = c0 + ty + i * 8;
        tile[ty + i * 8][tx] = Wh_[(size_t)c * HS + s0 + tx];
    }
    __syncthreads();
#pragma unroll
    for (int i = 0; i < 4; i++) {
        int sl = ty + i * 8;
        int row = z * 64 + s0 + sl;
        float v = tile[tx][sl];
        __nv_bfloat16 hi = __float2bfloat16(v);
        g_wth[(size_t)row * D_ + c0 + tx] = hi;
        g_wtl[(size_t)row * D_ + c0 + tx] = __float2bfloat16(v - __bfloat162float(hi));
    }
}

// ---------------------------------------------------------------------------
// bf16x3 GEMM via mma.sync: C[128 M][128 N] per CTA, K=1024.
// A[M,K] row-major (rows r0..), B[N,K] row-major (rows brow0..), C=A·B^T.
// 8 warps, warp tile 64x32. Kc=32, cp.async 2-stage pipeline.
// Smem rows padded to 40 bf16 (80 B): ldmatrix conflict-free.
// mode 0: scatter C to g_q/g_k/g_v.  mode 1: out = C + bias.
// ---------------------------------------------------------------------------
#define STAGE_B 40960   // 4 arrays * 128 rows * 80 B
#define GEMM_SMEM (2 * STAGE_B)
__global__ __launch_bounds__(256) void gemm_bf16x3(
    const __nv_bfloat16* __restrict__ Ah, const __nv_bfloat16* __restrict__ Al,
    const __nv_bfloat16* __restrict__ Bh, const __nv_bfloat16* __restrict__ Bl,
    const float* __restrict__ bias, float* __restrict__ out, int mode)
{
    extern __shared__ char smc[];
    const uint32_t sb = smem_u32(smc);
    const int tid = threadIdx.x;
    const int wid = tid >> 5, lane = tid & 31;
    const int wm = wid >> 2, wn = wid & 3;          // warp grid 2 x 4
    const int r0 = blockIdx.x * 128;
    const int brow0 = blockIdx.y * 128;

    // cp.async staging indices: u = tid + it*256 -> row = u>>2, seg = u&3
    const int ldrow = tid >> 2, ldseg = tid & 3;
    const uint32_t dst0 = (uint32_t)(ldrow * 80 + ldseg * 16);
    const size_t gao = (size_t)(r0 + ldrow) * D_ + ldseg * 8;
    const size_t gbo = (size_t)(brow0 + ldrow) * D_ + ldseg * 8;

#define LOAD_CHUNK(c, st) do {                                                  \
    uint32_t _b = sb + (st) * STAGE_B;                                          \
    int _kc = (c) * 32;                                                         \
    _Pragma("unroll")                                                           \
    for (int it = 0; it < 2; ++it) {                                            \
        uint32_t d = _b + dst0 + it * (64 * 80);                                \
        size_t ga = gao + _kc + (size_t)it * 64 * D_;                           \
        size_t gb = gbo + _kc + (size_t)it * 64 * D_;                           \
        cpasync16(d,              Ah + ga);                                     \
        cpasync16(d + 10240,      Al + ga);                                     \
        cpasync16(d + 20480,      Bh + gb);                                     \
        cpasync16(d + 30720,      Bl + gb);                                     \
    }                                                                           \
    asm volatile("cp.async.commit_group;" ::: "memory");                        \
} while (0)

    float acc[4][4][4] = {};

    // per-lane ldmatrix base offsets (row*80 + hi/lo 16B column select)
    const uint32_t lmA = (uint32_t)((wm * 64 + (lane & 15)) * 80 + (lane >> 4) * 16);
    const uint32_t lmB = (uint32_t)((wn * 32 + (lane & 15)) * 80 + (lane >> 4) * 16);

    LOAD_CHUNK(0, 0);
    LOAD_CHUNK(1, 1);

    for (int c = 0; c < 32; ++c) {
        asm volatile("cp.async.wait_group 1;" ::: "memory");
        __syncthreads();
        uint32_t base = sb + (c & 1) * STAGE_B;
#pragma unroll
        for (int kk = 0; kk < 2; ++kk) {
            uint32_t ko = (uint32_t)(kk * 32);
            uint32_t ah[4][4], al[4][4], bh[2][4], bl[2][4];
#pragma unroll
            for (int mt = 0; mt < 4; ++mt) {
                uint32_t a = base + lmA + mt * (16 * 80) + ko;
                ldmx4(ah[mt], a);
                ldmx4(al[mt], a + 10240);
            }
#pragma unroll
            for (int g = 0; g < 2; ++g) {
                uint32_t a = base + 20480 + lmB + g * (16 * 80) + ko;
                ldmx4(bh[g], a);
                ldmx4(bl[g], a + 10240);
            }
#pragma unroll
            for (int mt = 0; mt < 4; ++mt)
#pragma unroll
                for (int nt = 0; nt < 4; ++nt) {
                    int g = nt >> 1, od = nt & 1;
                    mma16816(acc[mt][nt], ah[mt], bh[g][od], bh[g][2 + od]);
                    mma16816(acc[mt][nt], ah[mt], bl[g][od], bl[g][2 + od]);
                    mma16816(acc[mt][nt], al[mt], bh[g][od], bh[g][2 + od]);
                }
        }
        __syncthreads();
        if (c + 2 < 32) LOAD_CHUNK(c + 2, c & 1);
        else asm volatile("cp.async.commit_group;" ::: "memory");
    }

    // epilogue: accumulator layout c0:(r=l/4, col=2(l%4)), c1:+1, c2:(r+8), c3:(r+8)+1
    const int erow = lane >> 2, ecol = (lane & 3) * 2;
#pragma unroll
    for (int mt = 0; mt < 4; ++mt) {
#pragma unroll
        for (int nt = 0; nt < 4; ++nt) {
            int gcol = brow0 + wn * 32 + nt * 8 + ecol;
            int grow = r0 + wm * 64 + mt * 16 + erow;
            if (mode == 0) {
                int m = gcol >> 10, rem = gcol & 1023;
                int h = rem >> 6, s = rem & 63;
                float* gsel = (m == 0) ? g_q : (m == 1) ? g_k : g_v;
#pragma unroll
                for (int half = 0; half < 2; ++half) {
                    int r = grow + half * 8;
                    int b = r >> 10, t = r & 1023;
                    float* dst = gsel + ((size_t)(b * H_ + h) * T_ + t) * HS + s;
                    *(float2*)dst = make_float2(acc[mt][nt][half * 2], acc[mt][nt][half * 2 + 1]);
                }
            } else {
                float2 bv = *(const float2*)(bias + gcol);
#pragma unroll
                for (int half = 0; half < 2; ++half) {
                    int r = grow + half * 8;
                    *(float2*)(out + (size_t)r * D_ + gcol) =
                        make_float2(acc[mt][nt][half * 2] + bv.x,
                                    acc[mt][nt][half * 2 + 1] + bv.y);
                }
            }
        }
    }
#undef LOAD_CHUNK
}

// ---------------------------------------------------------------------------
// causal flash attention (fp32, online softmax); epilogue emits bf16 hi/lo Y
// ---------------------------------------------------------------------------
#define ST 68
__global__ __launch_bounds__(256) void attn_kernel()
{
    extern __shared__ float sm_[];
    float* Qs = sm_;
    float* Ks = Qs + 64 * ST;
    float* Vs = Ks + 64 * ST;
    float* Ps = Vs + 64 * ST;

    const int qt = blockIdx.x;
    const int h  = blockIdx.y;
    const int b  = blockIdx.z;
    const int tx = threadIdx.x, ty = threadIdx.y;
    const int tid = ty * 16 + tx;

    const float* qp = g_q + ((size_t)(b * H_ + h) * T_ + qt * 64) * HS;
    const float* kp = g_k + (size_t)(b * H_ + h) * T_ * HS;
    const float* vp = g_v + (size_t)(b * H_ + h) * T_ * HS;

    {
        int c4 = (tid & 15) * 4, rr0 = tid >> 4;
#pragma unroll
        for (int r = 0; r < 4; r++) {
            int row = rr0 + r * 16;
            *(float4*)&Qs[row * ST + c4] = *(const float4*)&qp[(size_t)row * HS + c4];
        }
    }

    float m_i[4], l_i[4], o[4][4] = {};
#pragma unroll
    for (int i = 0; i < 4; i++) { m_i[i] = -INFINITY; l_i[i] = 0.f; }
    const float scale = 0.125f;

    for (int kt = 0; kt <= qt; kt++) {
        {
            const float* kpt = kp + (size_t)kt * 64 * HS;
            const float* vpt = vp + (size_t)kt * 64 * HS;
            int c4 = (tid & 15) * 4, rr0 = tid >> 4;
#pragma unroll
            for (int r = 0; r < 4; r++) {
                int row = rr0 + r * 16;
                *(float4*)&Ks[row * ST + c4] = *(const float4*)&kpt[(size_t)row * HS + c4];
                *(float4*)&Vs[row * ST + c4] = *(const float4*)&vpt[(size_t)row * HS + c4];
            }
        }
        __syncthreads();

        float s[4][4] = {};
#pragma unroll
        for (int ss = 0; ss < 64; ss += 4) {
            float4 q4[4], k4[4];
#pragma unroll
            for (int i = 0; i < 4; i++) q4[i] = *(const float4*)&Qs[(ty * 4 + i) * ST + ss];
#pragma unroll
            for (int j = 0; j < 4; j++) k4[j] = *(const float4*)&Ks[(tx * 4 + j) * ST + ss];
#pragma unroll
            for (int i = 0; i < 4; i++)
#pragma unroll
                for (int j = 0; j < 4; j++)
                    s[i][j] += q4[i].x * k4[j].x + q4[i].y * k4[j].y
                             + q4[i].z * k4[j].z + q4[i].w * k4[j].w;
        }

#pragma unroll
        for (int i = 0; i < 4; i++)
#pragma unroll
            for (int j = 0; j < 4; j++) {
                s[i][j] *= scale;
                if (kt == qt && (tx * 4 + j) > (ty * 4 + i)) s[i][j] = -INFINITY;
            }

        float mnew[4], corr[4];
#pragma unroll
        for (int i = 0; i < 4; i++) {
            float mx = fmaxf(fmaxf(s[i][0], s[i][1]), fmaxf(s[i][2], s[i][3]));
#pragma unroll
            for (int off = 8; off > 0; off >>= 1)
                mx = fmaxf(mx, __shfl_xor_sync(0xffffffffu, mx, off));
            mnew[i] = fmaxf(m_i[i], mx);
            corr[i] = __expf(m_i[i] - mnew[i]);
            m_i[i]  = mnew[i];
        }
#pragma unroll
        for (int i = 0; i < 4; i++) {
            float rs = 0.f;
#pragma unroll
            for (int j = 0; j < 4; j++) {
                float p = __expf(s[i][j] - mnew[i]);
                s[i][j] = p;
                rs += p;
            }
#pragma unroll
            for (int off = 8; off > 0; off >>= 1)
                rs += __shfl_xor_sync(0xffffffffu, rs, off);
            l_i[i] = l_i[i] * corr[i] + rs;
#pragma unroll
            for (int j = 0; j < 4; j++) o[i][j] *= corr[i];
        }

#pragma unroll
        for (int i = 0; i < 4; i++)
            *(float4*)&Ps[(ty * 4 + i) * ST + tx * 4] =
                make_float4(s[i][0], s[i][1], s[i][2], s[i][3]);
        __syncthreads();

#pragma unroll 8
        for (int kk = 0; kk < 64; kk++) {
            float p_[4];
#pragma unroll
            for (int i = 0; i < 4; i++) p_[i] = Ps[(ty * 4 + i) * ST + kk];
            float4 v4 = *(const float4*)&Vs[kk * ST + tx * 4];
#pragma unroll
            for (int i = 0; i < 4; i++) {
                o[i][0] += p_[i] * v4.x; o[i][1] += p_[i] * v4.y;
                o[i][2] += p_[i] * v4.z; o[i][3] += p_[i] * v4.w;
            }
        }
        __syncthreads();
    }

#pragma unroll
    for (int i = 0; i < 4; i++) {
        float inv = 1.f / l_i[i];
        int t = qt * 64 + ty * 4 + i;
        size_t base = ((size_t)b * T_ + t) * D_ + h * 64 + tx * 4;
        __nv_bfloat16 hh[4], ll[4];
#pragma unroll
        for (int j = 0; j < 4; j++) {
            float v = o[i][j] * inv;
            __nv_bfloat16 hi = __float2bfloat16(v);
            hh[j] = hi;
            ll[j] = __float2bfloat16(v - __bfloat162float(hi));
        }
        *(uint2*)&g_yh[base] = *(uint2*)hh;
        *(uint2*)&g_yl[base] = *(uint2*)ll;
    }
}

// ---------------------------------------------------------------------------
extern "C" void kernel_launch(void* const* d_in, const int* in_sizes, int n_in,
                              void* d_out, int out_size)
{
    const float* x  = (const float*)d_in[0];
    const float* Wq = (const float*)d_in[1];
    const float* Wk = (const float*)d_in[2];
    const float* Wv = (const float*)d_in[3];
    const float* Wo = (const float*)d_in[4];
    const float* bo = (const float*)d_in[5];
    float* out = (float*)d_out;

    cudaFuncSetAttribute(attn_kernel, cudaFuncAttributeMaxDynamicSharedMemorySize,
                         4 * 64 * ST * (int)sizeof(float));
    cudaFuncSetAttribute(gemm_bf16x3, cudaFuncAttributeMaxDynamicSharedMemorySize, GEMM_SMEM);

    __nv_bfloat16 *xh, *xl, *wth, *wtl, *yh, *yl, *woh, *wol;
    cudaGetSymbolAddress((void**)&xh,  g_xh);
    cudaGetSymbolAddress((void**)&xl,  g_xl);
    cudaGetSymbolAddress((void**)&wth, g_wth);
    cudaGetSymbolAddress((void**)&wtl, g_wtl);
    cudaGetSymbolAddress((void**)&yh,  g_yh);
    cudaGetSymbolAddress((void**)&yl,  g_yl);
    cudaGetSymbolAddress((void**)&woh, g_woh);
    cudaGetSymbolAddress((void**)&wol, g_wol);

    conv_pair<<<4096, 256>>>(x, xh, xl, B_ * T_ * D_);
    conv_wt<<<dim3(D_ / 32, HS / 32, 48), dim3(32, 8)>>>(Wq, Wk, Wv);
    conv_pair<<<1024, 256>>>(Wo, woh, wol, D_ * D_);

    // QKV: A = X[4096,1024], B = Wt[3072,1024] -> scatter to g_q/g_k/g_v
    gemm_bf16x3<<<dim3(32, 24), 256, GEMM_SMEM>>>(xh, xl, wth, wtl, bo, out, 0);

    attn_kernel<<<dim3(T_ / 64, H_, B_), dim3(16, 16), 4 * 64 * ST * (int)sizeof(float)>>>();

    // O-proj: A = Y[4096,1024], B = Wo[1024,1024] -> out + bias
    gemm_bf16x3<<<dim3(32, 8), 256, GEMM_SMEM>>>(yh, yl, woh, wol, bo, out, 1);
}

// round 5
// speedup vs baseline: 2.3781x; 1.5449x over previous
#include <cuda_runtime.h>
#include <cuda_bf16.h>
#include <cstdint>
#include <math.h>

#define B_ 4
#define T_ 1024
#define D_ 1024
#define H_ 16
#define HS 64

// ---------------- device scratch (allocation-free rule) ----------------
__device__ __nv_bfloat16 g_xh[B_*T_*D_];
__device__ __nv_bfloat16 g_xl[B_*T_*D_];
__device__ __nv_bfloat16 g_wth[3*H_*HS*D_];   // [m][h][s][c]  K-major
__device__ __nv_bfloat16 g_wtl[3*H_*HS*D_];
__device__ __nv_bfloat16 g_qh[B_*H_*T_*HS];   // pre-scaled by 0.125
__device__ __nv_bfloat16 g_ql[B_*H_*T_*HS];
__device__ __nv_bfloat16 g_kh[B_*H_*T_*HS];
__device__ __nv_bfloat16 g_kl[B_*H_*T_*HS];
__device__ __nv_bfloat16 g_vh[B_*H_*T_*HS];
__device__ __nv_bfloat16 g_vl[B_*H_*T_*HS];
__device__ __nv_bfloat16 g_yh[B_*T_*D_];
__device__ __nv_bfloat16 g_yl[B_*T_*D_];
__device__ __nv_bfloat16 g_woh[D_*D_];
__device__ __nv_bfloat16 g_wol[D_*D_];

// ---------------- helpers ----------------
__device__ __forceinline__ uint32_t smem_u32(const void* p) {
    uint32_t a;
    asm("{ .reg .u64 t; cvta.to.shared.u64 t, %1; cvt.u32.u64 %0, t; }" : "=r"(a) : "l"(p));
    return a;
}
__device__ __forceinline__ void cpasync16(uint32_t dst, const void* src) {
    asm volatile("cp.async.cg.shared.global [%0], [%1], 16;" :: "r"(dst), "l"(src) : "memory");
}
__device__ __forceinline__ void ldmx4(uint32_t* r, uint32_t addr) {
    asm volatile("ldmatrix.sync.aligned.m8n8.x4.shared.b16 {%0,%1,%2,%3}, [%4];"
                 : "=r"(r[0]), "=r"(r[1]), "=r"(r[2]), "=r"(r[3]) : "r"(addr));
}
__device__ __forceinline__ void ldmx4t(uint32_t* r, uint32_t addr) {
    asm volatile("ldmatrix.sync.aligned.m8n8.x4.trans.shared.b16 {%0,%1,%2,%3}, [%4];"
                 : "=r"(r[0]), "=r"(r[1]), "=r"(r[2]), "=r"(r[3]) : "r"(addr));
}
__device__ __forceinline__ void mma16816(float* d, const uint32_t* a, uint32_t b0, uint32_t b1) {
    asm volatile(
        "mma.sync.aligned.m16n8k16.row.col.f32.bf16.bf16.f32 "
        "{%0,%1,%2,%3}, {%4,%5,%6,%7}, {%8,%9}, {%0,%1,%2,%3};"
        : "+f"(d[0]), "+f"(d[1]), "+f"(d[2]), "+f"(d[3])
        : "r"(a[0]), "r"(a[1]), "r"(a[2]), "r"(a[3]), "r"(b0), "r"(b1));
}
__device__ __forceinline__ uint32_t packbf(float lo, float hi) {
    uint32_t d;
    asm("cvt.rn.bf16x2.f32 %0, %1, %2;" : "=r"(d) : "f"(hi), "f"(lo));
    return d;
}
__device__ __forceinline__ void split_pack(float v0, float v1, uint32_t& ph, uint32_t& pl) {
    __nv_bfloat16 h0 = __float2bfloat16(v0), h1 = __float2bfloat16(v1);
    __nv_bfloat162 hp; hp.x = h0; hp.y = h1;
    ph = *(uint32_t*)&hp;
    pl = packbf(v0 - __bfloat162float(h0), v1 - __bfloat162float(h1));
}

// ---------------------------------------------------------------------------
__global__ __launch_bounds__(256) void conv_pair(
    const float* __restrict__ src, __nv_bfloat16* __restrict__ dh,
    __nv_bfloat16* __restrict__ dl, int n)
{
    int i4 = (blockIdx.x * 256 + threadIdx.x) * 4;
    if (i4 >= n) return;
    float4 v = *(const float4*)(src + i4);
    float vv[4] = {v.x, v.y, v.z, v.w};
    __nv_bfloat16 hh[4], ll[4];
#pragma unroll
    for (int j = 0; j < 4; j++) {
        __nv_bfloat16 hi = __float2bfloat16(vv[j]);
        hh[j] = hi;
        ll[j] = __float2bfloat16(vv[j] - __bfloat162float(hi));
    }
    *(uint2*)(dh + i4) = *(uint2*)hh;
    *(uint2*)(dl + i4) = *(uint2*)ll;
}

// ---------------------------------------------------------------------------
__global__ __launch_bounds__(256) void conv_wt(
    const float* __restrict__ Wq, const float* __restrict__ Wk, const float* __restrict__ Wv)
{
    __shared__ float tile[32][33];
    int z = blockIdx.z;
    int m = z >> 4, h = z & 15;
    int c0 = blockIdx.x * 32, s0 = blockIdx.y * 32;
    int tx = threadIdx.x, ty = threadIdx.y;
    const float* W = (m == 0) ? Wq : (m == 1) ? Wk : Wv;
    const float* Wh_ = W + (size_t)h * D_ * HS;
#pragma unroll
    for (int i = 0; i < 4; i++) {
        int c = c0 + ty + i * 8;
        tile[ty + i * 8][tx] = Wh_[(size_t)c * HS + s0 + tx];
    }
    __syncthreads();
#pragma unroll
    for (int i = 0; i < 4; i++) {
        int sl = ty + i * 8;
        int row = z * 64 + s0 + sl;
        float v = tile[tx][sl];
        __nv_bfloat16 hi = __float2bfloat16(v);
        g_wth[(size_t)row * D_ + c0 + tx] = hi;
        g_wtl[(size_t)row * D_ + c0 + tx] = __float2bfloat16(v - __bfloat162float(hi));
    }
}

// ---------------------------------------------------------------------------
// bf16x3 GEMM via mma.sync (validated R3).
// ---------------------------------------------------------------------------
#define STAGE_B 40960
#define GEMM_SMEM (2 * STAGE_B)
__global__ __launch_bounds__(256) void gemm_bf16x3(
    const __nv_bfloat16* __restrict__ Ah, const __nv_bfloat16* __restrict__ Al,
    const __nv_bfloat16* __restrict__ Bh, const __nv_bfloat16* __restrict__ Bl,
    const float* __restrict__ bias, float* __restrict__ out, int mode)
{
    extern __shared__ char smc[];
    const uint32_t sb = smem_u32(smc);
    const int tid = threadIdx.x;
    const int wid = tid >> 5, lane = tid & 31;
    const int wm = wid >> 2, wn = wid & 3;
    const int r0 = blockIdx.x * 128;
    const int brow0 = blockIdx.y * 128;

    const int ldrow = tid >> 2, ldseg = tid & 3;
    const uint32_t dst0 = (uint32_t)(ldrow * 80 + ldseg * 16);
    const size_t gao = (size_t)(r0 + ldrow) * D_ + ldseg * 8;
    const size_t gbo = (size_t)(brow0 + ldrow) * D_ + ldseg * 8;

#define LOAD_CHUNK(c, st) do {                                                  \
    uint32_t _b = sb + (st) * STAGE_B;                                          \
    int _kc = (c) * 32;                                                         \
    _Pragma("unroll")                                                           \
    for (int it = 0; it < 2; ++it) {                                            \
        uint32_t d = _b + dst0 + it * (64 * 80);                                \
        size_t ga = gao + _kc + (size_t)it * 64 * D_;                           \
        size_t gb = gbo + _kc + (size_t)it * 64 * D_;                           \
        cpasync16(d,              Ah + ga);                                     \
        cpasync16(d + 10240,      Al + ga);                                     \
        cpasync16(d + 20480,      Bh + gb);                                     \
        cpasync16(d + 30720,      Bl + gb);                                     \
    }                                                                           \
    asm volatile("cp.async.commit_group;" ::: "memory");                        \
} while (0)

    float acc[4][4][4] = {};
    const uint32_t lmA = (uint32_t)((wm * 64 + (lane & 15)) * 80 + (lane >> 4) * 16);
    const uint32_t lmB = (uint32_t)((wn * 32 + (lane & 15)) * 80 + (lane >> 4) * 16);

    LOAD_CHUNK(0, 0);
    LOAD_CHUNK(1, 1);

    for (int c = 0; c < 32; ++c) {
        asm volatile("cp.async.wait_group 1;" ::: "memory");
        __syncthreads();
        uint32_t base = sb + (c & 1) * STAGE_B;
#pragma unroll
        for (int kk = 0; kk < 2; ++kk) {
            uint32_t ko = (uint32_t)(kk * 32);
            uint32_t ah[4][4], al[4][4], bh[2][4], bl[2][4];
#pragma unroll
            for (int mt = 0; mt < 4; ++mt) {
                uint32_t a = base + lmA + mt * (16 * 80) + ko;
                ldmx4(ah[mt], a);
                ldmx4(al[mt], a + 10240);
            }
#pragma unroll
            for (int g = 0; g < 2; ++g) {
                uint32_t a = base + 20480 + lmB + g * (16 * 80) + ko;
                ldmx4(bh[g], a);
                ldmx4(bl[g], a + 10240);
            }
#pragma unroll
            for (int mt = 0; mt < 4; ++mt)
#pragma unroll
                for (int nt = 0; nt < 4; ++nt) {
                    int g = nt >> 1, od = nt & 1;
                    mma16816(acc[mt][nt], ah[mt], bh[g][od], bh[g][2 + od]);
                    mma16816(acc[mt][nt], ah[mt], bl[g][od], bl[g][2 + od]);
                    mma16816(acc[mt][nt], al[mt], bh[g][od], bh[g][2 + od]);
                }
        }
        __syncthreads();
        if (c + 2 < 32) LOAD_CHUNK(c + 2, c & 1);
        else asm volatile("cp.async.commit_group;" ::: "memory");
    }

    const int erow = lane >> 2, ecol = (lane & 3) * 2;
#pragma unroll
    for (int mt = 0; mt < 4; ++mt) {
#pragma unroll
        for (int nt = 0; nt < 4; ++nt) {
            int gcol = brow0 + wn * 32 + nt * 8 + ecol;
            int grow = r0 + wm * 64 + mt * 16 + erow;
            if (mode == 0) {
                int m = gcol >> 10, rem = gcol & 1023;
                int h = rem >> 6, s = rem & 63;
                __nv_bfloat16* dh = (m == 0) ? g_qh : (m == 1) ? g_kh : g_vh;
                __nv_bfloat16* dl = (m == 0) ? g_ql : (m == 1) ? g_kl : g_vl;
                float sc = (m == 0) ? 0.125f : 1.0f;
#pragma unroll
                for (int half = 0; half < 2; ++half) {
                    int r = grow + half * 8;
                    int b = r >> 10, t = r & 1023;
                    size_t idx = ((size_t)(b * H_ + h) * T_ + t) * HS + s;
                    uint32_t ph, pl;
                    split_pack(acc[mt][nt][half * 2] * sc, acc[mt][nt][half * 2 + 1] * sc, ph, pl);
                    *(uint32_t*)(dh + idx) = ph;
                    *(uint32_t*)(dl + idx) = pl;
                }
            } else {
                float2 bv = *(const float2*)(bias + gcol);
#pragma unroll
                for (int half = 0; half < 2; ++half) {
                    int r = grow + half * 8;
                    *(float2*)(out + (size_t)r * D_ + gcol) =
                        make_float2(acc[mt][nt][half * 2] + bv.x,
                                    acc[mt][nt][half * 2 + 1] + bv.y);
                }
            }
        }
    }
#undef LOAD_CHUNK
}

// ---------------------------------------------------------------------------
// Tensor-core causal flash attention. grid (8, H, B) block 256 (8 warps).
// 128-query tile per CTA, 64-key tiles, bf16x3 S and PV, fp32 softmax.
// ---------------------------------------------------------------------------
#define AT_PITCH 144
#define AT_ARR 9216           // 64 rows * 144 B
#define AT_STAGE 36864        // Kh,Kl,Vh,Vl
#define AT_SMEM (2 * AT_STAGE)
__global__ __launch_bounds__(256) void attn_mma()
{
    extern __shared__ char smc[];
    const uint32_t sb = smem_u32(smc);
    const int tid = threadIdx.x, wid = tid >> 5, lane = tid & 31;
    const int qt = 7 - blockIdx.x;           // longest first
    const int h = blockIdx.y, b = blockIdx.z;
    const int bh = b * H_ + h;
    const size_t bhoff = (size_t)bh * T_ * HS;

    const __nv_bfloat16* qh = g_qh + bhoff + (size_t)qt * 128 * HS;
    const __nv_bfloat16* ql = g_ql + bhoff + (size_t)qt * 128 * HS;
    const __nv_bfloat16* kh = g_kh + bhoff;
    const __nv_bfloat16* kl = g_kl + bhoff;
    const __nv_bfloat16* vh = g_vh + bhoff;
    const __nv_bfloat16* vl = g_vl + bhoff;

    // ---- stage Q (hi at 0, lo at 18432) then ldmatrix into registers ----
#pragma unroll
    for (int it = 0; it < 4; ++it) {
        int u = tid + it * 256;
        int row = u >> 3, seg = u & 7;
        uint32_t d = (uint32_t)(row * AT_PITCH + seg * 16);
        *(uint4*)(smc + d)         = *(const uint4*)(qh + row * HS + seg * 8);
        *(uint4*)(smc + 18432 + d) = *(const uint4*)(ql + row * HS + seg * 8);
    }
    __syncthreads();
    uint32_t aqh[4][4], aql[4][4];
    {
        uint32_t qa = sb + (uint32_t)((wid * 16 + (lane & 15)) * AT_PITCH + (lane >> 4) * 16);
#pragma unroll
        for (int kk = 0; kk < 4; ++kk) {
            ldmx4(aqh[kk], qa + kk * 32);
            ldmx4(aql[kk], qa + 18432 + kk * 32);
        }
    }
    __syncthreads();

    const int nkt = 2 * qt + 2;
    // K/V staging: 4 threads per 64-elem row; thread q covers 16B chunks q and q+4
    const int lrow = tid >> 2, lq = tid & 3;

#define LOADKV(kt, st) do {                                                     \
    uint32_t _d = sb + (st) * AT_STAGE + (uint32_t)(lrow * AT_PITCH + lq * 16);  \
    size_t _so = (size_t)((kt) * 64 + lrow) * HS + lq * 8;                      \
    cpasync16(_d,                 kh + _so); cpasync16(_d + 64,                 kh + _so + 32); \
    cpasync16(_d + AT_ARR,        kl + _so); cpasync16(_d + AT_ARR + 64,        kl + _so + 32); \
    cpasync16(_d + 2 * AT_ARR,    vh + _so); cpasync16(_d + 2 * AT_ARR + 64,    vh + _so + 32); \
    cpasync16(_d + 3 * AT_ARR,    vl + _so); cpasync16(_d + 3 * AT_ARR + 64,    vl + _so + 32); \
    asm volatile("cp.async.commit_group;" ::: "memory");                        \
} while (0)

    float o[8][4] = {};
    float m0 = -INFINITY, m1 = -INFINITY, l0 = 0.f, l1 = 0.f;
    const int r0 = lane >> 2, c0l = (lane & 3) * 2;
    const int qrow0 = qt * 128 + wid * 16 + r0;

    LOADKV(0, 0);
    LOADKV(1, 1);

    for (int kt = 0; kt < nkt; ++kt) {
        asm volatile("cp.async.wait_group 1;" ::: "memory");
        __syncthreads();
        uint32_t kb = sb + (kt & 1) * AT_STAGE;

        // ---- S = Q K^T (bf16x3) ----
        float sa[8][4] = {};
#pragma unroll
        for (int kk = 0; kk < 4; ++kk) {
#pragma unroll
            for (int g = 0; g < 4; ++g) {
                uint32_t a = kb + (uint32_t)((g * 16 + (lane & 15)) * AT_PITCH + kk * 32 + (lane >> 4) * 16);
                uint32_t bhf[4], blf[4];
                ldmx4(bhf, a);
                ldmx4(blf, a + AT_ARR);
#pragma unroll
                for (int od = 0; od < 2; ++od) {
                    int nt = g * 2 + od;
                    mma16816(sa[nt], aqh[kk], bhf[od], bhf[2 + od]);
                    mma16816(sa[nt], aqh[kk], blf[od], blf[2 + od]);
                    mma16816(sa[nt], aql[kk], bhf[od], bhf[2 + od]);
                }
            }
        }

        // ---- mask (diagonal tiles only) ----
        if (kt >= 2 * qt) {
#pragma unroll
            for (int nt = 0; nt < 8; ++nt) {
                int colb = kt * 64 + nt * 8 + c0l;
                if (colb > qrow0)     sa[nt][0] = -INFINITY;
                if (colb + 1 > qrow0) sa[nt][1] = -INFINITY;
                if (colb > qrow0 + 8)     sa[nt][2] = -INFINITY;
                if (colb + 1 > qrow0 + 8) sa[nt][3] = -INFINITY;
            }
        }

        // ---- online softmax (fp32) ----
        float mx0 = -INFINITY, mx1 = -INFINITY;
#pragma unroll
        for (int nt = 0; nt < 8; ++nt) {
            mx0 = fmaxf(mx0, fmaxf(sa[nt][0], sa[nt][1]));
            mx1 = fmaxf(mx1, fmaxf(sa[nt][2], sa[nt][3]));
        }
        mx0 = fmaxf(mx0, __shfl_xor_sync(0xffffffffu, mx0, 1));
        mx0 = fmaxf(mx0, __shfl_xor_sync(0xffffffffu, mx0, 2));
        mx1 = fmaxf(mx1, __shfl_xor_sync(0xffffffffu, mx1, 1));
        mx1 = fmaxf(mx1, __shfl_xor_sync(0xffffffffu, mx1, 2));
        float mn0 = fmaxf(m0, mx0), mn1 = fmaxf(m1, mx1);
        float cr0 = __expf(m0 - mn0), cr1 = __expf(m1 - mn1);
        m0 = mn0; m1 = mn1;
        float ls0 = 0.f, ls1 = 0.f;
#pragma unroll
        for (int nt = 0; nt < 8; ++nt) {
            sa[nt][0] = __expf(sa[nt][0] - mn0); ls0 += sa[nt][0];
            sa[nt][1] = __expf(sa[nt][1] - mn0); ls0 += sa[nt][1];
            sa[nt][2] = __expf(sa[nt][2] - mn1); ls1 += sa[nt][2];
            sa[nt][3] = __expf(sa[nt][3] - mn1); ls1 += sa[nt][3];
        }
        ls0 += __shfl_xor_sync(0xffffffffu, ls0, 1);
        ls0 += __shfl_xor_sync(0xffffffffu, ls0, 2);
        ls1 += __shfl_xor_sync(0xffffffffu, ls1, 1);
        ls1 += __shfl_xor_sync(0xffffffffu, ls1, 2);
        l0 = l0 * cr0 + ls0;
        l1 = l1 * cr1 + ls1;
#pragma unroll
        for (int nt = 0; nt < 8; ++nt) {
            o[nt][0] *= cr0; o[nt][1] *= cr0;
            o[nt][2] *= cr1; o[nt][3] *= cr1;
        }

        // ---- O += P V (bf16x3; V via ldmatrix.trans) ----
#pragma unroll
        for (int kk = 0; kk < 4; ++kk) {
            uint32_t ph[4], pl[4];
            split_pack(sa[2 * kk][0],     sa[2 * kk][1],     ph[0], pl[0]);
            split_pack(sa[2 * kk][2],     sa[2 * kk][3],     ph[1], pl[1]);
            split_pack(sa[2 * kk + 1][0], sa[2 * kk + 1][1], ph[2], pl[2]);
            split_pack(sa[2 * kk + 1][2], sa[2 * kk + 1][3], ph[3], pl[3]);
#pragma unroll
            for (int jj = 0; jj < 4; ++jj) {
                uint32_t a = kb + 2 * AT_ARR +
                    (uint32_t)((kk * 16 + (lane & 15)) * AT_PITCH + jj * 32 + (lane >> 4) * 16);
                uint32_t vhf[4], vlf[4];
                ldmx4t(vhf, a);
                ldmx4t(vlf, a + AT_ARR);
                mma16816(o[jj * 2], ph, vhf[0], vhf[1]);
                mma16816(o[jj * 2], ph, vlf[0], vlf[1]);
                mma16816(o[jj * 2], pl, vhf[0], vhf[1]);
                mma16816(o[jj * 2 + 1], ph, vhf[2], vhf[3]);
                mma16816(o[jj * 2 + 1], ph, vlf[2], vlf[3]);
                mma16816(o[jj * 2 + 1], pl, vhf[2], vhf[3]);
            }
        }
        __syncthreads();
        if (kt + 2 < nkt) LOADKV(kt + 2, kt & 1);
        else asm volatile("cp.async.commit_group;" ::: "memory");
    }

    // ---- epilogue: normalize, split to bf16 hi/lo Y ----
    float inv0 = 1.f / l0, inv1 = 1.f / l1;
#pragma unroll
    for (int nt = 0; nt < 8; ++nt) {
        int col = nt * 8 + c0l;
        size_t i0 = ((size_t)b * T_ + qrow0) * D_ + h * 64 + col;
        size_t i1 = i0 + (size_t)8 * D_;
        uint32_t ph, pl;
        split_pack(o[nt][0] * inv0, o[nt][1] * inv0, ph, pl);
        *(uint32_t*)(g_yh + i0) = ph;
        *(uint32_t*)(g_yl + i0) = pl;
        split_pack(o[nt][2] * inv1, o[nt][3] * inv1, ph, pl);
        *(uint32_t*)(g_yh + i1) = ph;
        *(uint32_t*)(g_yl + i1) = pl;
    }
#undef LOADKV
}

// ---------------------------------------------------------------------------
extern "C" void kernel_launch(void* const* d_in, const int* in_sizes, int n_in,
                              void* d_out, int out_size)
{
    const float* x  = (const float*)d_in[0];
    const float* Wq = (const float*)d_in[1];
    const float* Wk = (const float*)d_in[2];
    const float* Wv = (const float*)d_in[3];
    const float* Wo = (const float*)d_in[4];
    const float* bo = (const float*)d_in[5];
    float* out = (float*)d_out;

    cudaFuncSetAttribute(gemm_bf16x3, cudaFuncAttributeMaxDynamicSharedMemorySize, GEMM_SMEM);
    cudaFuncSetAttribute(attn_mma, cudaFuncAttributeMaxDynamicSharedMemorySize, AT_SMEM);

    __nv_bfloat16 *xh, *xl, *wth, *wtl, *yh, *yl, *woh, *wol;
    cudaGetSymbolAddress((void**)&xh,  g_xh);
    cudaGetSymbolAddress((void**)&xl,  g_xl);
    cudaGetSymbolAddress((void**)&wth, g_wth);
    cudaGetSymbolAddress((void**)&wtl, g_wtl);
    cudaGetSymbolAddress((void**)&yh,  g_yh);
    cudaGetSymbolAddress((void**)&yl,  g_yl);
    cudaGetSymbolAddress((void**)&woh, g_woh);
    cudaGetSymbolAddress((void**)&wol, g_wol);

    conv_pair<<<4096, 256>>>(x, xh, xl, B_ * T_ * D_);
    conv_wt<<<dim3(D_ / 32, HS / 32, 48), dim3(32, 8)>>>(Wq, Wk, Wv);
    conv_pair<<<1024, 256>>>(Wo, woh, wol, D_ * D_);

    // QKV: A = X[4096,1024], B = Wt[3072,1024] -> bf16 hi/lo q/k/v
    gemm_bf16x3<<<dim3(32, 24), 256, GEMM_SMEM>>>(xh, xl, wth, wtl, bo, out, 0);

    attn_mma<<<dim3(8, H_, B_), 256, AT_SMEM>>>();

    // O-proj: A = Y[4096,1024], B = Wo[1024,1024] -> out + bias
    gemm_bf16x3<<<dim3(32, 8), 256, GEMM_SMEM>>>(yh, yl, woh, wol, bo, out, 1);
}

// round 6
// speedup vs baseline: 2.5852x; 1.0871x over previous
#include <cuda_runtime.h>
#include <cuda_bf16.h>
#include <cstdint>
#include <math.h>

#define B_ 4
#define T_ 1024
#define D_ 1024
#define H_ 16
#define HS 64

// ---------------- device scratch (allocation-free rule) ----------------
__device__ __nv_bfloat16 g_xh[B_*T_*D_];
__device__ __nv_bfloat16 g_xl[B_*T_*D_];
__device__ __nv_bfloat16 g_wth[3*H_*HS*D_];   // [m][h][s][c]  K-major
__device__ __nv_bfloat16 g_wtl[3*H_*HS*D_];
__device__ __nv_bfloat16 g_qh[B_*H_*T_*HS];   // pre-scaled by 0.125
__device__ __nv_bfloat16 g_ql[B_*H_*T_*HS];
__device__ __nv_bfloat16 g_kh[B_*H_*T_*HS];
__device__ __nv_bfloat16 g_kl[B_*H_*T_*HS];
__device__ __nv_bfloat16 g_vh[B_*H_*T_*HS];
__device__ __nv_bfloat16 g_vl[B_*H_*T_*HS];
__device__ __nv_bfloat16 g_yh[B_*T_*D_];
__device__ __nv_bfloat16 g_yl[B_*T_*D_];
__device__ __nv_bfloat16 g_woh[D_*D_];
__device__ __nv_bfloat16 g_wol[D_*D_];

// ---------------- helpers ----------------
__device__ __forceinline__ uint32_t smem_u32(const void* p) {
    uint32_t a;
    asm("{ .reg .u64 t; cvta.to.shared.u64 t, %1; cvt.u32.u64 %0, t; }" : "=r"(a) : "l"(p));
    return a;
}
__device__ __forceinline__ void cpasync16(uint32_t dst, const void* src) {
    asm volatile("cp.async.cg.shared.global [%0], [%1], 16;" :: "r"(dst), "l"(src) : "memory");
}
__device__ __forceinline__ void ldmx4(uint32_t* r, uint32_t addr) {
    asm volatile("ldmatrix.sync.aligned.m8n8.x4.shared.b16 {%0,%1,%2,%3}, [%4];"
                 : "=r"(r[0]), "=r"(r[1]), "=r"(r[2]), "=r"(r[3]) : "r"(addr));
}
__device__ __forceinline__ void ldmx4t(uint32_t* r, uint32_t addr) {
    asm volatile("ldmatrix.sync.aligned.m8n8.x4.trans.shared.b16 {%0,%1,%2,%3}, [%4];"
                 : "=r"(r[0]), "=r"(r[1]), "=r"(r[2]), "=r"(r[3]) : "r"(addr));
}
__device__ __forceinline__ void mma16816(float* d, const uint32_t* a, uint32_t b0, uint32_t b1) {
    asm volatile(
        "mma.sync.aligned.m16n8k16.row.col.f32.bf16.bf16.f32 "
        "{%0,%1,%2,%3}, {%4,%5,%6,%7}, {%8,%9}, {%0,%1,%2,%3};"
        : "+f"(d[0]), "+f"(d[1]), "+f"(d[2]), "+f"(d[3])
        : "r"(a[0]), "r"(a[1]), "r"(a[2]), "r"(a[3]), "r"(b0), "r"(b1));
}
__device__ __forceinline__ uint32_t packbf(float lo, float hi) {
    uint32_t d;
    asm("cvt.rn.bf16x2.f32 %0, %1, %2;" : "=r"(d) : "f"(hi), "f"(lo));
    return d;
}
__device__ __forceinline__ void split_pack(float v0, float v1, uint32_t& ph, uint32_t& pl) {
    __nv_bfloat16 h0 = __float2bfloat16(v0), h1 = __float2bfloat16(v1);
    __nv_bfloat162 hp; hp.x = h0; hp.y = h1;
    ph = *(uint32_t*)&hp;
    pl = packbf(v0 - __bfloat162float(h0), v1 - __bfloat162float(h1));
}

// ---------------------------------------------------------------------------
__global__ __launch_bounds__(256) void conv_pair(
    const float* __restrict__ src, __nv_bfloat16* __restrict__ dh,
    __nv_bfloat16* __restrict__ dl, int n)
{
    int i4 = (blockIdx.x * 256 + threadIdx.x) * 4;
    if (i4 >= n) return;
    float4 v = *(const float4*)(src + i4);
    float vv[4] = {v.x, v.y, v.z, v.w};
    __nv_bfloat16 hh[4], ll[4];
#pragma unroll
    for (int j = 0; j < 4; j++) {
        __nv_bfloat16 hi = __float2bfloat16(vv[j]);
        hh[j] = hi;
        ll[j] = __float2bfloat16(vv[j] - __bfloat162float(hi));
    }
    *(uint2*)(dh + i4) = *(uint2*)hh;
    *(uint2*)(dl + i4) = *(uint2*)ll;
}

// ---------------------------------------------------------------------------
__global__ __launch_bounds__(256) void conv_wt(
    const float* __restrict__ Wq, const float* __restrict__ Wk, const float* __restrict__ Wv)
{
    __shared__ float tile[32][33];
    int z = blockIdx.z;
    int m = z >> 4, h = z & 15;
    int c0 = blockIdx.x * 32, s0 = blockIdx.y * 32;
    int tx = threadIdx.x, ty = threadIdx.y;
    const float* W = (m == 0) ? Wq : (m == 1) ? Wk : Wv;
    const float* Wh_ = W + (size_t)h * D_ * HS;
#pragma unroll
    for (int i = 0; i < 4; i++) {
        int c = c0 + ty + i * 8;
        tile[ty + i * 8][tx] = Wh_[(size_t)c * HS + s0 + tx];
    }
    __syncthreads();
#pragma unroll
    for (int i = 0; i < 4; i++) {
        int sl = ty + i * 8;
        int row = z * 64 + s0 + sl;
        float v = tile[tx][sl];
        __nv_bfloat16 hi = __float2bfloat16(v);
        g_wth[(size_t)row * D_ + c0 + tx] = hi;
        g_wtl[(size_t)row * D_ + c0 + tx] = __float2bfloat16(v - __bfloat162float(hi));
    }
}

// ---------------------------------------------------------------------------
// bf16x3 GEMM via mma.sync, templated on MODE to keep epilogue regs separate.
// MODE 0: QKV -> bf16 hi/lo scatter (q scaled 0.125). MODE 1: out = C + bias.
// ---------------------------------------------------------------------------
#define STAGE_B 40960
#define GEMM_SMEM (2 * STAGE_B)
template <int MODE>
__global__ __launch_bounds__(256, 2) void gemm_bf16x3(
    const __nv_bfloat16* __restrict__ Ah, const __nv_bfloat16* __restrict__ Al,
    const __nv_bfloat16* __restrict__ Bh, const __nv_bfloat16* __restrict__ Bl,
    const float* __restrict__ bias, float* __restrict__ out)
{
    extern __shared__ char smc[];
    const uint32_t sb = smem_u32(smc);
    const int tid = threadIdx.x;
    const int wid = tid >> 5, lane = tid & 31;
    const int wm = wid >> 2, wn = wid & 3;
    const int r0 = blockIdx.x * 128;
    const int brow0 = blockIdx.y * 128;

    const int ldrow = tid >> 2, ldseg = tid & 3;
    const uint32_t dst0 = (uint32_t)(ldrow * 80 + ldseg * 16);
    const size_t gao = (size_t)(r0 + ldrow) * D_ + ldseg * 8;
    const size_t gbo = (size_t)(brow0 + ldrow) * D_ + ldseg * 8;

#define LOAD_CHUNK(c, st) do {                                                  \
    uint32_t _b = sb + (st) * STAGE_B;                                          \
    int _kc = (c) * 32;                                                         \
    _Pragma("unroll")                                                           \
    for (int it = 0; it < 2; ++it) {                                            \
        uint32_t d = _b + dst0 + it * (64 * 80);                                \
        size_t ga = gao + _kc + (size_t)it * 64 * D_;                           \
        size_t gb = gbo + _kc + (size_t)it * 64 * D_;                           \
        cpasync16(d,              Ah + ga);                                     \
        cpasync16(d + 10240,      Al + ga);                                     \
        cpasync16(d + 20480,      Bh + gb);                                     \
        cpasync16(d + 30720,      Bl + gb);                                     \
    }                                                                           \
    asm volatile("cp.async.commit_group;" ::: "memory");                        \
} while (0)

    float acc[4][4][4] = {};
    const uint32_t lmA = (uint32_t)((wm * 64 + (lane & 15)) * 80 + (lane >> 4) * 16);
    const uint32_t lmB = (uint32_t)((wn * 32 + (lane & 15)) * 80 + (lane >> 4) * 16);

    LOAD_CHUNK(0, 0);
    LOAD_CHUNK(1, 1);

    for (int c = 0; c < 32; ++c) {
        asm volatile("cp.async.wait_group 1;" ::: "memory");
        __syncthreads();
        uint32_t base = sb + (c & 1) * STAGE_B;
#pragma unroll
        for (int kk = 0; kk < 2; ++kk) {
            uint32_t ko = (uint32_t)(kk * 32);
            uint32_t ah[4][4], al[4][4], bh[2][4], bl[2][4];
#pragma unroll
            for (int mt = 0; mt < 4; ++mt) {
                uint32_t a = base + lmA + mt * (16 * 80) + ko;
                ldmx4(ah[mt], a);
                ldmx4(al[mt], a + 10240);
            }
#pragma unroll
            for (int g = 0; g < 2; ++g) {
                uint32_t a = base + 20480 + lmB + g * (16 * 80) + ko;
                ldmx4(bh[g], a);
                ldmx4(bl[g], a + 10240);
            }
#pragma unroll
            for (int mt = 0; mt < 4; ++mt)
#pragma unroll
                for (int nt = 0; nt < 4; ++nt) {
                    int g = nt >> 1, od = nt & 1;
                    mma16816(acc[mt][nt], ah[mt], bh[g][od], bh[g][2 + od]);
                    mma16816(acc[mt][nt], ah[mt], bl[g][od], bl[g][2 + od]);
                    mma16816(acc[mt][nt], al[mt], bh[g][od], bh[g][2 + od]);
                }
        }
        __syncthreads();
        if (c + 2 < 32) LOAD_CHUNK(c + 2, c & 1);
        else asm volatile("cp.async.commit_group;" ::: "memory");
    }

    const int erow = lane >> 2, ecol = (lane & 3) * 2;
#pragma unroll
    for (int mt = 0; mt < 4; ++mt) {
#pragma unroll
        for (int nt = 0; nt < 4; ++nt) {
            int gcol = brow0 + wn * 32 + nt * 8 + ecol;
            int grow = r0 + wm * 64 + mt * 16 + erow;
            if (MODE == 0) {
                int m = gcol >> 10, rem = gcol & 1023;
                int h = rem >> 6, s = rem & 63;
                __nv_bfloat16* dh = (m == 0) ? g_qh : (m == 1) ? g_kh : g_vh;
                __nv_bfloat16* dl = (m == 0) ? g_ql : (m == 1) ? g_kl : g_vl;
                float sc = (m == 0) ? 0.125f : 1.0f;
#pragma unroll
                for (int half = 0; half < 2; ++half) {
                    int r = grow + half * 8;
                    int b = r >> 10, t = r & 1023;
                    size_t idx = ((size_t)(b * H_ + h) * T_ + t) * HS + s;
                    uint32_t ph, pl;
                    split_pack(acc[mt][nt][half * 2] * sc, acc[mt][nt][half * 2 + 1] * sc, ph, pl);
                    *(uint32_t*)(dh + idx) = ph;
                    *(uint32_t*)(dl + idx) = pl;
                }
            } else {
                float2 bv = *(const float2*)(bias + gcol);
#pragma unroll
                for (int half = 0; half < 2; ++half) {
                    int r = grow + half * 8;
                    *(float2*)(out + (size_t)r * D_ + gcol) =
                        make_float2(acc[mt][nt][half * 2] + bv.x,
                                    acc[mt][nt][half * 2 + 1] + bv.y);
                }
            }
        }
    }
#undef LOAD_CHUNK
}

// ---------------------------------------------------------------------------
// Tensor-core causal flash attention (validated R5).
// ---------------------------------------------------------------------------
#define AT_PITCH 144
#define AT_ARR 9216
#define AT_STAGE 36864
#define AT_SMEM (2 * AT_STAGE)
__global__ __launch_bounds__(256) void attn_mma()
{
    extern __shared__ char smc[];
    const uint32_t sb = smem_u32(smc);
    const int tid = threadIdx.x, wid = tid >> 5, lane = tid & 31;
    const int qt = 7 - blockIdx.x;
    const int h = blockIdx.y, b = blockIdx.z;
    const int bh = b * H_ + h;
    const size_t bhoff = (size_t)bh * T_ * HS;

    const __nv_bfloat16* qh = g_qh + bhoff + (size_t)qt * 128 * HS;
    const __nv_bfloat16* ql = g_ql + bhoff + (size_t)qt * 128 * HS;
    const __nv_bfloat16* kh = g_kh + bhoff;
    const __nv_bfloat16* kl = g_kl + bhoff;
    const __nv_bfloat16* vh = g_vh + bhoff;
    const __nv_bfloat16* vl = g_vl + bhoff;

#pragma unroll
    for (int it = 0; it < 4; ++it) {
        int u = tid + it * 256;
        int row = u >> 3, seg = u & 7;
        uint32_t d = (uint32_t)(row * AT_PITCH + seg * 16);
        *(uint4*)(smc + d)         = *(const uint4*)(qh + row * HS + seg * 8);
        *(uint4*)(smc + 18432 + d) = *(const uint4*)(ql + row * HS + seg * 8);
    }
    __syncthreads();
    uint32_t aqh[4][4], aql[4][4];
    {
        uint32_t qa = sb + (uint32_t)((wid * 16 + (lane & 15)) * AT_PITCH + (lane >> 4) * 16);
#pragma unroll
        for (int kk = 0; kk < 4; ++kk) {
            ldmx4(aqh[kk], qa + kk * 32);
            ldmx4(aql[kk], qa + 18432 + kk * 32);
        }
    }
    __syncthreads();

    const int nkt = 2 * qt + 2;
    const int lrow = tid >> 2, lq = tid & 3;

#define LOADKV(kt, st) do {                                                     \
    uint32_t _d = sb + (st) * AT_STAGE + (uint32_t)(lrow * AT_PITCH + lq * 16);  \
    size_t _so = (size_t)((kt) * 64 + lrow) * HS + lq * 8;                      \
    cpasync16(_d,                 kh + _so); cpasync16(_d + 64,                 kh + _so + 32); \
    cpasync16(_d + AT_ARR,        kl + _so); cpasync16(_d + AT_ARR + 64,        kl + _so + 32); \
    cpasync16(_d + 2 * AT_ARR,    vh + _so); cpasync16(_d + 2 * AT_ARR + 64,    vh + _so + 32); \
    cpasync16(_d + 3 * AT_ARR,    vl + _so); cpasync16(_d + 3 * AT_ARR + 64,    vl + _so + 32); \
    asm volatile("cp.async.commit_group;" ::: "memory");                        \
} while (0)

    float o[8][4] = {};
    float m0 = -INFINITY, m1 = -INFINITY, l0 = 0.f, l1 = 0.f;
    const int r0 = lane >> 2, c0l = (lane & 3) * 2;
    const int qrow0 = qt * 128 + wid * 16 + r0;

    LOADKV(0, 0);
    LOADKV(1, 1);

    for (int kt = 0; kt < nkt; ++kt) {
        asm volatile("cp.async.wait_group 1;" ::: "memory");
        __syncthreads();
        uint32_t kb = sb + (kt & 1) * AT_STAGE;

        float sa[8][4] = {};
#pragma unroll
        for (int kk = 0; kk < 4; ++kk) {
#pragma unroll
            for (int g = 0; g < 4; ++g) {
                uint32_t a = kb + (uint32_t)((g * 16 + (lane & 15)) * AT_PITCH + kk * 32 + (lane >> 4) * 16);
                uint32_t bhf[4], blf[4];
                ldmx4(bhf, a);
                ldmx4(blf, a + AT_ARR);
#pragma unroll
                for (int od = 0; od < 2; ++od) {
                    int nt = g * 2 + od;
                    mma16816(sa[nt], aqh[kk], bhf[od], bhf[2 + od]);
                    mma16816(sa[nt], aqh[kk], blf[od], blf[2 + od]);
                    mma16816(sa[nt], aql[kk], bhf[od], bhf[2 + od]);
                }
            }
        }

        if (kt >= 2 * qt) {
#pragma unroll
            for (int nt = 0; nt < 8; ++nt) {
                int colb = kt * 64 + nt * 8 + c0l;
                if (colb > qrow0)     sa[nt][0] = -INFINITY;
                if (colb + 1 > qrow0) sa[nt][1] = -INFINITY;
                if (colb > qrow0 + 8)     sa[nt][2] = -INFINITY;
                if (colb + 1 > qrow0 + 8) sa[nt][3] = -INFINITY;
            }
        }

        float mx0 = -INFINITY, mx1 = -INFINITY;
#pragma unroll
        for (int nt = 0; nt < 8; ++nt) {
            mx0 = fmaxf(mx0, fmaxf(sa[nt][0], sa[nt][1]));
            mx1 = fmaxf(mx1, fmaxf(sa[nt][2], sa[nt][3]));
        }
        mx0 = fmaxf(mx0, __shfl_xor_sync(0xffffffffu, mx0, 1));
        mx0 = fmaxf(mx0, __shfl_xor_sync(0xffffffffu, mx0, 2));
        mx1 = fmaxf(mx1, __shfl_xor_sync(0xffffffffu, mx1, 1));
        mx1 = fmaxf(mx1, __shfl_xor_sync(0xffffffffu, mx1, 2));
        float mn0 = fmaxf(m0, mx0), mn1 = fmaxf(m1, mx1);
        float cr0 = __expf(m0 - mn0), cr1 = __expf(m1 - mn1);
        m0 = mn0; m1 = mn1;
        float ls0 = 0.f, ls1 = 0.f;
#pragma unroll
        for (int nt = 0; nt < 8; ++nt) {
            sa[nt][0] = __expf(sa[nt][0] - mn0); ls0 += sa[nt][0];
            sa[nt][1] = __expf(sa[nt][1] - mn0); ls0 += sa[nt][1];
            sa[nt][2] = __expf(sa[nt][2] - mn1); ls1 += sa[nt][2];
            sa[nt][3] = __expf(sa[nt][3] - mn1); ls1 += sa[nt][3];
        }
        ls0 += __shfl_xor_sync(0xffffffffu, ls0, 1);
        ls0 += __shfl_xor_sync(0xffffffffu, ls0, 2);
        ls1 += __shfl_xor_sync(0xffffffffu, ls1, 1);
        ls1 += __shfl_xor_sync(0xffffffffu, ls1, 2);
        l0 = l0 * cr0 + ls0;
        l1 = l1 * cr1 + ls1;
#pragma unroll
        for (int nt = 0; nt < 8; ++nt) {
            o[nt][0] *= cr0; o[nt][1] *= cr0;
            o[nt][2] *= cr1; o[nt][3] *= cr1;
        }

#pragma unroll
        for (int kk = 0; kk < 4; ++kk) {
            uint32_t ph[4], pl[4];
            split_pack(sa[2 * kk][0],     sa[2 * kk][1],     ph[0], pl[0]);
            split_pack(sa[2 * kk][2],     sa[2 * kk][3],     ph[1], pl[1]);
            split_pack(sa[2 * kk + 1][0], sa[2 * kk + 1][1], ph[2], pl[2]);
            split_pack(sa[2 * kk + 1][2], sa[2 * kk + 1][3], ph[3], pl[3]);
#pragma unroll
            for (int jj = 0; jj < 4; ++jj) {
                uint32_t a = kb + 2 * AT_ARR +
                    (uint32_t)((kk * 16 + (lane & 15)) * AT_PITCH + jj * 32 + (lane >> 4) * 16);
                uint32_t vhf[4], vlf[4];
                ldmx4t(vhf, a);
                ldmx4t(vlf, a + AT_ARR);
                mma16816(o[jj * 2], ph, vhf[0], vhf[1]);
                mma16816(o[jj * 2], ph, vlf[0], vlf[1]);
                mma16816(o[jj * 2], pl, vhf[0], vhf[1]);
                mma16816(o[jj * 2 + 1], ph, vhf[2], vhf[3]);
                mma16816(o[jj * 2 + 1], ph, vlf[2], vlf[3]);
                mma16816(o[jj * 2 + 1], pl, vhf[2], vhf[3]);
            }
        }
        __syncthreads();
        if (kt + 2 < nkt) LOADKV(kt + 2, kt & 1);
        else asm volatile("cp.async.commit_group;" ::: "memory");
    }

    float inv0 = 1.f / l0, inv1 = 1.f / l1;
#pragma unroll
    for (int nt = 0; nt < 8; ++nt) {
        int col = nt * 8 + c0l;
        size_t i0 = ((size_t)b * T_ + qrow0) * D_ + h * 64 + col;
        size_t i1 = i0 + (size_t)8 * D_;
        uint32_t ph, pl;
        split_pack(o[nt][0] * inv0, o[nt][1] * inv0, ph, pl);
        *(uint32_t*)(g_yh + i0) = ph;
        *(uint32_t*)(g_yl + i0) = pl;
        split_pack(o[nt][2] * inv1, o[nt][3] * inv1, ph, pl);
        *(uint32_t*)(g_yh + i1) = ph;
        *(uint32_t*)(g_yl + i1) = pl;
    }
#undef LOADKV
}

// ---------------------------------------------------------------------------
extern "C" void kernel_launch(void* const* d_in, const int* in_sizes, int n_in,
                              void* d_out, int out_size)
{
    const float* x  = (const float*)d_in[0];
    const float* Wq = (const float*)d_in[1];
    const float* Wk = (const float*)d_in[2];
    const float* Wv = (const float*)d_in[3];
    const float* Wo = (const float*)d_in[4];
    const float* bo = (const float*)d_in[5];
    float* out = (float*)d_out;

    cudaFuncSetAttribute(gemm_bf16x3<0>, cudaFuncAttributeMaxDynamicSharedMemorySize, GEMM_SMEM);
    cudaFuncSetAttribute(gemm_bf16x3<1>, cudaFuncAttributeMaxDynamicSharedMemorySize, GEMM_SMEM);
    cudaFuncSetAttribute(attn_mma, cudaFuncAttributeMaxDynamicSharedMemorySize, AT_SMEM);

    __nv_bfloat16 *xh, *xl, *wth, *wtl, *yh, *yl, *woh, *wol;
    cudaGetSymbolAddress((void**)&xh,  g_xh);
    cudaGetSymbolAddress((void**)&xl,  g_xl);
    cudaGetSymbolAddress((void**)&wth, g_wth);
    cudaGetSymbolAddress((void**)&wtl, g_wtl);
    cudaGetSymbolAddress((void**)&yh,  g_yh);
    cudaGetSymbolAddress((void**)&yl,  g_yl);
    cudaGetSymbolAddress((void**)&woh, g_woh);
    cudaGetSymbolAddress((void**)&wol, g_wol);

    conv_pair<<<4096, 256>>>(x, xh, xl, B_ * T_ * D_);
    conv_wt<<<dim3(D_ / 32, HS / 32, 48), dim3(32, 8)>>>(Wq, Wk, Wv);
    conv_pair<<<1024, 256>>>(Wo, woh, wol, D_ * D_);

    gemm_bf16x3<0><<<dim3(32, 24), 256, GEMM_SMEM>>>(xh, xl, wth, wtl, bo, out);

    attn_mma<<<dim3(8, H_, B_), 256, AT_SMEM>>>();

    gemm_bf16x3<1><<<dim3(32, 8), 256, GEMM_SMEM>>>(yh, yl, woh, wol, bo, out);
}